// round 1
// baseline (speedup 1.0000x reference)
#include <cuda_runtime.h>
#include <stdint.h>

// Instant-NGP hash-grid encode + fused MLP 32->64->64->3, fp32, f32x2-packed FMA.

#define HASHMAP_SIZE (1u << 17)
#define N_LEVELS 16

// scales[l] = 16 * 1.5^l = 3^l * 2^(4-l); exactly representable in fp32 up to l=15.
__device__ __constant__ float SCALES[16] = {
    16.0f, 24.0f, 36.0f, 54.0f, 81.0f, 121.5f, 182.25f, 273.375f,
    410.0625f, 615.09375f, 922.640625f, 1383.9609375f,
    2075.94140625f, 3113.912109375f, 4670.8681640625f, 7006.30224609375f
};

// Packed dual-fp32 FMA (sm_100+). ptxas never emits this from C++; explicit PTX.
__device__ __forceinline__ float2 ffma2(float2 a, float2 b, float2 c) {
    float2 d;
    asm("{\n\t"
        ".reg .b64 ra, rb, rc, rd;\n\t"
        "mov.b64 ra, {%2, %3};\n\t"
        "mov.b64 rb, {%4, %5};\n\t"
        "mov.b64 rc, {%6, %7};\n\t"
        "fma.rn.f32x2 rd, ra, rb, rc;\n\t"
        "mov.b64 {%0, %1}, rd;\n\t"
        "}"
        : "=f"(d.x), "=f"(d.y)
        : "f"(a.x), "f"(a.y), "f"(b.x), "f"(b.y), "f"(c.x), "f"(c.y));
    return d;
}

__global__ void __launch_bounds__(128)
fused_mlp_kernel(const float2* __restrict__ x,
                 const float*  __restrict__ enc,
                 const float*  __restrict__ w0, const float* __restrict__ b0,
                 const float*  __restrict__ w1, const float* __restrict__ b1,
                 const float*  __restrict__ w2, const float* __restrict__ b2,
                 float* __restrict__ out, int N)
{
    // Weights staged in shared; all per-thread weight reads are warp-uniform broadcasts.
    __shared__ float2 sw0[32 * 32];   // w0 [32,64] row-major, as float2 pairs: 8 KB
    __shared__ float2 sw1[64 * 32];   // w1 [64,64]: 16 KB
    __shared__ float  sw2[64 * 3];    // w2 [64,3]
    __shared__ float  sb0[64], sb1[64], sb2[4];

    const int tid = threadIdx.x;
    for (int i = tid; i < 32 * 32; i += 128) sw0[i] = ((const float2*)w0)[i];
    for (int i = tid; i < 64 * 32; i += 128) sw1[i] = ((const float2*)w1)[i];
    for (int i = tid; i < 64 * 3;  i += 128) sw2[i] = w2[i];
    if (tid < 64) { sb0[tid] = b0[tid]; sb1[tid] = b1[tid]; }
    if (tid < 3)  { sb2[tid] = b2[tid]; }
    __syncthreads();

    const int gi = blockIdx.x * 128 + tid;
    if (gi >= N) return;

    const float2 xi = x[gi];

    // ---------------- Hash-grid encode: 16 levels x 2 features ----------------
    float feat[32];
    #pragma unroll
    for (int l = 0; l < N_LEVELS; l++) {
        const float s  = SCALES[l];
        const float px = xi.x * s;
        const float py = xi.y * s;
        const float fx = floorf(px);
        const float fy = floorf(py);
        const float tx = px - fx;
        const float ty = py - fy;
        const unsigned ix0 = (unsigned)fx;
        const unsigned iy0 = (unsigned)fy;

        float accx = 0.0f, accy = 0.0f;
        // Corner order matches reference: (cx,cy) = (0,0),(0,1),(1,0),(1,1)
        #pragma unroll
        for (int c = 0; c < 4; c++) {
            const unsigned cx = (unsigned)(c >> 1);
            const unsigned cy = (unsigned)(c & 1);
            const unsigned h   = (ix0 + cx) ^ ((iy0 + cy) * 2654435761u);
            const unsigned idx = h & (HASHMAP_SIZE - 1u);
            const float2 e = *(const float2*)(enc + ((idx * 16u + (unsigned)l) * 2u));
            const float wx = cx ? tx : (1.0f - tx);
            const float wy = cy ? ty : (1.0f - ty);
            const float w  = wx * wy;
            accx = fmaf(w, e.x, accx);
            accy = fmaf(w, e.y, accy);
        }
        feat[2 * l + 0] = accx;
        feat[2 * l + 1] = accy;
    }

    // ---------------- Layer 1: [32] -> relu[64], packed f32x2 ----------------
    float2 h0[32];
    #pragma unroll
    for (int j = 0; j < 32; j++)
        h0[j] = make_float2(sb0[2 * j], sb0[2 * j + 1]);
    #pragma unroll
    for (int k = 0; k < 32; k++) {
        const float2 a = make_float2(feat[k], feat[k]);
        #pragma unroll
        for (int j = 0; j < 32; j++)
            h0[j] = ffma2(a, sw0[k * 32 + j], h0[j]);
    }
    #pragma unroll
    for (int j = 0; j < 32; j++) {
        h0[j].x = fmaxf(h0[j].x, 0.0f);
        h0[j].y = fmaxf(h0[j].y, 0.0f);
    }

    // ------- Layer 2 (in two 32-wide halves) + fused Layer 3 accumulate -------
    float o0 = sb2[0], o1 = sb2[1], o2 = sb2[2];
    #pragma unroll
    for (int half = 0; half < 2; half++) {
        float2 h1[16];
        #pragma unroll
        for (int j = 0; j < 16; j++)
            h1[j] = make_float2(sb1[32 * half + 2 * j], sb1[32 * half + 2 * j + 1]);
        #pragma unroll
        for (int k = 0; k < 64; k++) {
            const float a = (k & 1) ? h0[k >> 1].y : h0[k >> 1].x;
            const float2 av = make_float2(a, a);
            #pragma unroll
            for (int j = 0; j < 16; j++)
                h1[j] = ffma2(av, sw1[k * 32 + 16 * half + j], h1[j]);
        }
        #pragma unroll
        for (int j = 0; j < 16; j++) {
            const float v0 = fmaxf(h1[j].x, 0.0f);
            const float v1 = fmaxf(h1[j].y, 0.0f);
            const int r0 = 32 * half + 2 * j;
            const int r1 = r0 + 1;
            o0 = fmaf(v0, sw2[r0 * 3 + 0], o0);
            o1 = fmaf(v0, sw2[r0 * 3 + 1], o1);
            o2 = fmaf(v0, sw2[r0 * 3 + 2], o2);
            o0 = fmaf(v1, sw2[r1 * 3 + 0], o0);
            o1 = fmaf(v1, sw2[r1 * 3 + 1], o1);
            o2 = fmaf(v1, sw2[r1 * 3 + 2], o2);
        }
    }

    out[gi * 3 + 0] = o0;
    out[gi * 3 + 1] = o1;
    out[gi * 3 + 2] = o2;
}

extern "C" void kernel_launch(void* const* d_in, const int* in_sizes, int n_in,
                              void* d_out, int out_size)
{
    const float2* x   = (const float2*)d_in[0];
    const float*  enc = (const float*) d_in[1];
    const float*  w0  = (const float*) d_in[2];
    const float*  b0  = (const float*) d_in[3];
    const float*  w1  = (const float*) d_in[4];
    const float*  b1  = (const float*) d_in[5];
    const float*  w2  = (const float*) d_in[6];
    const float*  b2  = (const float*) d_in[7];
    float* out = (float*)d_out;

    const int N = in_sizes[0] / 2;
    const int threads = 128;
    const int blocks = (N + threads - 1) / threads;
    fused_mlp_kernel<<<blocks, threads>>>(x, enc, w0, b0, w1, b1, w2, b2, out, N);
}